// round 2
// baseline (speedup 1.0000x reference)
#include <cuda_runtime.h>
#include <math.h>

#define DIMC   2048
#define NH     16
#define HD     128
#define T_SEQ  512
#define BATCH  16
#define BH     (BATCH * NH)      // 256
#define NTOK   (BATCH * T_SEQ)   // 8192
#define N_QKV  (3 * DIMC)        // 6144

// Scratch (device globals; no allocations allowed)
__device__ float g_Q[BH * T_SEQ * HD];   // [B,H,T,hd]
__device__ float g_K[BH * T_SEQ * HD];
__device__ float g_V[BH * T_SEQ * HD];
__device__ float g_Y[NTOK * DIMC];       // [B,T,C] attention output

// ---------------------------------------------------------------------------
// SGEMM: 128x128 block tile, BK=16, 256 threads, 8x8 per thread.
// MODE 0: A=x, B=Wqkv, scatter epilogue into g_Q/g_K/g_V ([B,H,T,hd])
// MODE 1: A=g_Y, B=Wout, C=out
// ---------------------------------------------------------------------------
template <int MODE>
__global__ __launch_bounds__(256, 2)
void sgemm_kernel(const float* __restrict__ Aparam,
                  const float* __restrict__ Bmat,
                  float* __restrict__ Cmat,
                  int N, int K)
{
    const int BM = 128, BN = 128, BK = 16;
    __shared__ float As[BK][BM + 4];
    __shared__ float Bs[BK][BN + 4];

    const float* A = (MODE == 0) ? Aparam : g_Y;

    int tid = threadIdx.x;
    int bm = blockIdx.y * BM;
    int bn = blockIdx.x * BN;

    int tm = tid / 16;          // 0..15
    int tn = tid % 16;          // 0..15

    float acc[8][8];
#pragma unroll
    for (int i = 0; i < 8; i++)
#pragma unroll
        for (int j = 0; j < 8; j++) acc[i][j] = 0.f;

    int arow = tid / 4;         // 0..63  (+64 second iter)
    int acol = (tid % 4) * 4;   // 0,4,8,12
    int brow = tid / 32;        // 0..7   (+8 second iter)
    int bcol = (tid % 32) * 4;  // 0..124

    const float* Aptr = A + (long)bm * K;
    const float* Bptr = Bmat + bn;

    for (int k0 = 0; k0 < K; k0 += BK) {
#pragma unroll
        for (int i = 0; i < 2; i++) {
            int r = arow + i * 64;
            float4 v = *(const float4*)(Aptr + (long)r * K + k0 + acol);
            As[acol + 0][r] = v.x;
            As[acol + 1][r] = v.y;
            As[acol + 2][r] = v.z;
            As[acol + 3][r] = v.w;
        }
#pragma unroll
        for (int i = 0; i < 2; i++) {
            int r = brow + i * 8;
            float4 v = *(const float4*)(Bptr + (long)(k0 + r) * N + bcol);
            *(float4*)&Bs[r][bcol] = v;
        }
        __syncthreads();

#pragma unroll
        for (int kk = 0; kk < BK; kk++) {
            float a0[4], a1[4], b0[4], b1[4];
            *(float4*)a0 = *(const float4*)&As[kk][tm * 4];
            *(float4*)a1 = *(const float4*)&As[kk][64 + tm * 4];
            *(float4*)b0 = *(const float4*)&Bs[kk][tn * 4];
            *(float4*)b1 = *(const float4*)&Bs[kk][64 + tn * 4];
#pragma unroll
            for (int i = 0; i < 4; i++) {
#pragma unroll
                for (int j = 0; j < 4; j++) {
                    acc[i][j]         += a0[i] * b0[j];
                    acc[i][j + 4]     += a0[i] * b1[j];
                    acc[i + 4][j]     += a1[i] * b0[j];
                    acc[i + 4][j + 4] += a1[i] * b1[j];
                }
            }
        }
        __syncthreads();
    }

    // Epilogue
#pragma unroll
    for (int i = 0; i < 8; i++) {
        int rloc = (i < 4) ? (tm * 4 + i) : (64 + tm * 4 + (i - 4));
        int grow = bm + rloc;   // token index
#pragma unroll
        for (int j = 0; j < 8; j++) {
            int cloc = (j < 4) ? (tn * 4 + j) : (64 + tn * 4 + (j - 4));
            int gcol = bn + cloc;
            float v = acc[i][j];
            if (MODE == 0) {
                int which = gcol >> 11;        // 0=q 1=k 2=v
                int rem = gcol & 2047;
                int h = rem >> 7;
                int d = rem & 127;
                int b = grow >> 9;
                int t = grow & 511;
                float* dst = (which == 0) ? g_Q : (which == 1) ? g_K : g_V;
                dst[(((long)(b * NH + h)) * T_SEQ + t) * HD + d] = v;
            } else {
                Cmat[(long)grow * N + gcol] = v;
            }
        }
    }
}

// ---------------------------------------------------------------------------
// RoPE in-place on g_Q, g_K (first 16 dims of each head).
// One thread handles one (b,h,t, pair-index i in 0..7).
// ---------------------------------------------------------------------------
__global__ void rope_kernel()
{
    int idx = blockIdx.x * blockDim.x + threadIdx.x;
    const int total = BH * T_SEQ * 8;
    if (idx >= total) return;
    int i = idx & 7;
    int bht = idx >> 3;
    int t = bht % T_SEQ;

    float inv = powf(10000.0f, -(float)i / 8.0f);  // 10000^{-(2i)/16}
    float fr = (float)t * inv;
    float s, c;
    sincosf(fr, &s, &c);

    float* q = g_Q + (long)bht * HD;
    float x1 = q[i], x2 = q[i + 8];
    q[i]     = x1 * c - x2 * s;
    q[i + 8] = x2 * c + x1 * s;

    float* k = g_K + (long)bht * HD;
    x1 = k[i]; x2 = k[i + 8];
    k[i]     = x1 * c - x2 * s;
    k[i + 8] = x2 * c + x1 * s;
}

// ---------------------------------------------------------------------------
// Flash attention, causal, fp32. Block = 8 warps = 8 consecutive queries.
// K/V staged through 32-key smem tiles; warp-per-query online softmax.
// Lane l owns output dims {l, l+32, l+64, l+96}.
// ---------------------------------------------------------------------------
__global__ __launch_bounds__(256)
void flash_kernel()
{
    const int TK = 32;
    __shared__ float Ks[TK][HD];
    __shared__ float Vs[TK][HD];

    int bh = blockIdx.y;
    int q0 = blockIdx.x * 8;
    int w = threadIdx.x >> 5;
    int lane = threadIdx.x & 31;
    int qidx = q0 + w;

    const float* qptr = g_Q + ((long)bh * T_SEQ + qidx) * HD;
    float qr[4], o[4] = {0.f, 0.f, 0.f, 0.f};
#pragma unroll
    for (int i = 0; i < 4; i++) qr[i] = qptr[lane + 32 * i];

    float m = -INFINITY, ssum = 0.f;
    const float scale = 0.08838834764831845f;  // 1/sqrt(128)

    int nT = (q0 + 8 + TK - 1) / TK;
    const float* Kb = g_K + (long)bh * T_SEQ * HD;
    const float* Vb = g_V + (long)bh * T_SEQ * HD;

    for (int tile = 0; tile < nT; tile++) {
        int k0 = tile * TK;
        for (int i = threadIdx.x; i < TK * HD / 4; i += 256) {
            int r = i >> 5;
            int c = (i & 31) * 4;
            *(float4*)&Ks[r][c] = *(const float4*)(Kb + (long)(k0 + r) * HD + c);
            *(float4*)&Vs[r][c] = *(const float4*)(Vb + (long)(k0 + r) * HD + c);
        }
        __syncthreads();

        if (k0 <= qidx) {
            int kmax = min(TK, qidx - k0 + 1);
            for (int kk = 0; kk < kmax; kk++) {
                float p = qr[0] * Ks[kk][lane]      + qr[1] * Ks[kk][lane + 32]
                        + qr[2] * Ks[kk][lane + 64] + qr[3] * Ks[kk][lane + 96];
                p += __shfl_xor_sync(0xffffffffu, p, 16);
                p += __shfl_xor_sync(0xffffffffu, p, 8);
                p += __shfl_xor_sync(0xffffffffu, p, 4);
                p += __shfl_xor_sync(0xffffffffu, p, 2);
                p += __shfl_xor_sync(0xffffffffu, p, 1);
                float s = p * scale;
                float newm = fmaxf(m, s);
                float alpha = __expf(m - newm);
                float pe = __expf(s - newm);
                ssum = ssum * alpha + pe;
#pragma unroll
                for (int i = 0; i < 4; i++)
                    o[i] = o[i] * alpha + pe * Vs[kk][lane + 32 * i];
                m = newm;
            }
        }
        __syncthreads();
    }

    float invs = 1.0f / ssum;
    int b = bh >> 4, h = bh & 15;
    float* yp = g_Y + ((long)(b * T_SEQ + qidx)) * DIMC + h * HD;
#pragma unroll
    for (int i = 0; i < 4; i++) yp[lane + 32 * i] = o[i] * invs;
}

// ---------------------------------------------------------------------------
extern "C" void kernel_launch(void* const* d_in, const int* in_sizes, int n_in,
                              void* d_out, int out_size)
{
    const float* x    = (const float*)d_in[0];   // [16,512,2048]
    const float* Wqkv = (const float*)d_in[1];   // [2048,6144]
    const float* Wout = (const float*)d_in[2];   // [2048,2048]
    float* out = (float*)d_out;                  // [16,512,2048]

    // 1) QKV projection with scatter to [B,H,T,hd]
    {
        dim3 grid(N_QKV / 128, NTOK / 128);  // 48 x 64
        sgemm_kernel<0><<<grid, 256>>>(x, Wqkv, nullptr, N_QKV, DIMC);
    }
    // 2) RoPE on Q,K
    {
        int total = BH * T_SEQ * 8;
        rope_kernel<<<(total + 255) / 256, 256>>>();
    }
    // 3) Causal flash attention -> g_Y [B,T,C]
    {
        dim3 grid(T_SEQ / 8, BH);            // 64 x 256
        flash_kernel<<<grid, 256>>>();
    }
    // 4) Output projection
    {
        dim3 grid(DIMC / 128, NTOK / 128);   // 16 x 64
        sgemm_kernel<1><<<grid, 256>>>(nullptr, Wout, out, DIMC, DIMC);
    }
}

// round 4
// speedup vs baseline: 1.9773x; 1.9773x over previous
#include <cuda_runtime.h>
#include <math.h>

#define DIMC   2048
#define NH     16
#define HD     128
#define T_SEQ  512
#define BATCH  16
#define BH     (BATCH * NH)      // 256
#define NTOK   (BATCH * T_SEQ)   // 8192
#define N_QKV  (3 * DIMC)        // 6144
#define GKD    2048              // GEMM K dim (both GEMMs)

// Scratch (device globals; no allocations allowed)
__device__ float g_Q[BH * T_SEQ * HD];
__device__ float g_K[BH * T_SEQ * HD];
__device__ float g_V[BH * T_SEQ * HD];
__device__ float g_Y[NTOK * DIMC];        // attention output, tf32-rounded at write
__device__ float g_xr[NTOK * DIMC];       // x rounded to tf32
__device__ float g_WqkvT[N_QKV * DIMC];   // [6144][2048], tf32-rounded
__device__ float g_WoutT[DIMC * DIMC];    // [2048][2048], tf32-rounded

// ---------------------------------------------------------------------------
__device__ __forceinline__ float to_tf32(float x) {
    float y;
    asm("cvt.rna.tf32.f32 %0, %1;" : "=f"(y) : "f"(x));
    return y;
}

__device__ __forceinline__ unsigned smem_u32(const void* p) {
    unsigned a;
    asm("{ .reg .u64 t; cvta.to.shared.u64 t, %1; cvt.u32.u64 %0, t; }"
        : "=r"(a) : "l"(p));
    return a;
}

// ---------------------------------------------------------------------------
// Pre-round x to tf32 (float4 vectorized)
// ---------------------------------------------------------------------------
__global__ void round_x_kernel(const float* __restrict__ x)
{
    int i = blockIdx.x * blockDim.x + threadIdx.x;      // float4 index
    float4 v = *(const float4*)(x + (long)i * 4);
    v.x = to_tf32(v.x); v.y = to_tf32(v.y);
    v.z = to_tf32(v.z); v.w = to_tf32(v.w);
    *(float4*)(g_xr + (long)i * 4) = v;
}

// ---------------------------------------------------------------------------
// Transpose + round: Wt[n][k] = tf32(W[k][n])
// ---------------------------------------------------------------------------
template <int WHICH>  // 0: Wqkv -> g_WqkvT, 1: Wout -> g_WoutT
__global__ void transpose_kernel(const float* __restrict__ W, int K, int N)
{
    __shared__ float t[32][33];
    float* Wt = (WHICH == 0) ? g_WqkvT : g_WoutT;
    int n0 = blockIdx.x * 32, k0 = blockIdx.y * 32;
    int tx = threadIdx.x, ty = threadIdx.y;  // 32 x 8
#pragma unroll
    for (int i = 0; i < 32; i += 8)
        t[ty + i][tx] = to_tf32(W[(long)(k0 + ty + i) * N + n0 + tx]);
    __syncthreads();
#pragma unroll
    for (int i = 0; i < 32; i += 8)
        Wt[(long)(n0 + ty + i) * K + k0 + tx] = t[tx][ty + i];
}

// ---------------------------------------------------------------------------
// TF32 mma.sync GEMM: C[M,N] = A[M,K] * Bt[N,K]^T,  K=2048.
// BM=128 BN=128 BK=32, 256 thr, warps 4(M) x 2(N), warp tile 32x64.
// cp.async double-buffered. Smem tiles padded to 36 floats/row.
// MODE 0: A=g_xr, Bt=g_WqkvT, scatter -> g_Q/g_K/g_V [B,H,T,hd]
// MODE 1: A=g_Y,  Bt=g_WoutT, C=out
// ---------------------------------------------------------------------------
#define BKP 36
#define TILE_F (128 * BKP)            // floats per A (or B) tile = 4608
#define STAGE_F (2 * TILE_F)          // 9216 floats per stage
#define GEMM_SMEM (2 * STAGE_F * 4)   // 73728 bytes

template <int MODE>
__global__ __launch_bounds__(256, 2)
void gemm_mma_kernel(float* __restrict__ Cmat, int N)
{
    extern __shared__ float sm[];

    const float* A  = (MODE == 0) ? g_xr : g_Y;
    const float* Bt = (MODE == 0) ? g_WqkvT : g_WoutT;

    int tid = threadIdx.x;
    int wid = tid >> 5;
    int lane = tid & 31;
    int g = lane >> 2;        // group id 0..7
    int tig = lane & 3;       // thread-in-group

    int bm = blockIdx.y * 128;
    int bn = blockIdx.x * 128;
    int wm = (wid & 3) * 32;  // warp M offset
    int wn = (wid >> 2) * 64; // warp N offset

    const float* Arow = A + (long)bm * GKD;
    const float* Brow = Bt + (long)bn * GKD;

    float acc[2][8][4];
#pragma unroll
    for (int mt = 0; mt < 2; mt++)
#pragma unroll
        for (int nt = 0; nt < 8; nt++)
#pragma unroll
            for (int v = 0; v < 4; v++) acc[mt][nt][v] = 0.f;

    // ---- stage loader (cp.async) ----
    auto load_stage = [&](int it, int st) {
        float* dstA = sm + st * STAGE_F;
        float* dstB = dstA + TILE_F;
        int k0 = it * 32;
#pragma unroll
        for (int i = 0; i < 4; i++) {
            int id = tid + 256 * i;          // 0..1023
            int r = id >> 3, ch = id & 7;
            unsigned da = smem_u32(dstA + r * BKP + ch * 4);
            const float* sa = Arow + (long)r * GKD + k0 + ch * 4;
            asm volatile("cp.async.cg.shared.global [%0], [%1], 16;"
                         :: "r"(da), "l"(sa));
            unsigned db = smem_u32(dstB + r * BKP + ch * 4);
            const float* sb = Brow + (long)r * GKD + k0 + ch * 4;
            asm volatile("cp.async.cg.shared.global [%0], [%1], 16;"
                         :: "r"(db), "l"(sb));
        }
        asm volatile("cp.async.commit_group;" ::: "memory");
    };

    // ---- per-stage compute ----
    auto compute = [&](const float* s) {
        const float* As = s;
        const float* Bs = s + TILE_F;
#pragma unroll
        for (int ks = 0; ks < 32; ks += 8) {
            unsigned a[2][4];
#pragma unroll
            for (int mt = 0; mt < 2; mt++) {
                int r = wm + 16 * mt + g;
                a[mt][0] = __float_as_uint(As[r * BKP + ks + tig]);
                a[mt][1] = __float_as_uint(As[(r + 8) * BKP + ks + tig]);
                a[mt][2] = __float_as_uint(As[r * BKP + ks + tig + 4]);
                a[mt][3] = __float_as_uint(As[(r + 8) * BKP + ks + tig + 4]);
            }
#pragma unroll
            for (int nt = 0; nt < 8; nt++) {
                int rn = wn + 8 * nt + g;
                unsigned b0 = __float_as_uint(Bs[rn * BKP + ks + tig]);
                unsigned b1 = __float_as_uint(Bs[rn * BKP + ks + tig + 4]);
#pragma unroll
                for (int mt = 0; mt < 2; mt++) {
                    asm volatile(
                        "mma.sync.aligned.m16n8k8.row.col.f32.tf32.tf32.f32 "
                        "{%0,%1,%2,%3}, {%4,%5,%6,%7}, {%8,%9}, {%0,%1,%2,%3};"
                        : "+f"(acc[mt][nt][0]), "+f"(acc[mt][nt][1]),
                          "+f"(acc[mt][nt][2]), "+f"(acc[mt][nt][3])
                        : "r"(a[mt][0]), "r"(a[mt][1]), "r"(a[mt][2]), "r"(a[mt][3]),
                          "r"(b0), "r"(b1));
                }
            }
        }
    };

    const int NIT = GKD / 32;     // 64
    load_stage(0, 0);
    load_stage(1, 1);

    for (int it = 0; it < NIT; it++) {
        if (it < NIT - 1)
            asm volatile("cp.async.wait_group 1;" ::: "memory");
        else
            asm volatile("cp.async.wait_group 0;" ::: "memory");
        __syncthreads();
        compute(sm + (it & 1) * STAGE_F);
        __syncthreads();
        if (it + 2 < NIT) load_stage(it + 2, it & 1);
    }

    // ---- epilogue ----
#pragma unroll
    for (int mt = 0; mt < 2; mt++) {
#pragma unroll
        for (int nt = 0; nt < 8; nt++) {
            int col = bn + wn + 8 * nt + 2 * tig;
#pragma unroll
            for (int half = 0; half < 2; half++) {     // row g / g+8
                int m = bm + wm + 16 * mt + g + 8 * half;
                float2 v = make_float2(acc[mt][nt][2 * half],
                                       acc[mt][nt][2 * half + 1]);
                if (MODE == 0) {
                    int which = col >> 11;
                    int rm = col & 2047;
                    int h = rm >> 7, d = rm & 127;
                    float* dst = (which == 0) ? g_Q : (which == 1) ? g_K : g_V;
                    *(float2*)(dst + (((long)((m >> 9) * NH + h)) * T_SEQ
                                      + (m & 511)) * HD + d) = v;
                } else {
                    *(float2*)(Cmat + (long)m * N + col) = v;
                }
            }
        }
    }
}

// ---------------------------------------------------------------------------
// RoPE in-place on g_Q, g_K (first 16 dims of each head).
// ---------------------------------------------------------------------------
__global__ void rope_kernel()
{
    int idx = blockIdx.x * blockDim.x + threadIdx.x;
    const int total = BH * T_SEQ * 8;
    if (idx >= total) return;
    int i = idx & 7;
    int bht = idx >> 3;
    int t = bht % T_SEQ;

    float inv = powf(10000.0f, -(float)i / 8.0f);
    float fr = (float)t * inv;
    float s, c;
    sincosf(fr, &s, &c);

    float* q = g_Q + (long)bht * HD;
    float x1 = q[i], x2 = q[i + 8];
    q[i]     = x1 * c - x2 * s;
    q[i + 8] = x2 * c + x1 * s;

    float* k = g_K + (long)bht * HD;
    x1 = k[i]; x2 = k[i + 8];
    k[i]     = x1 * c - x2 * s;
    k[i + 8] = x2 * c + x1 * s;
}

// ---------------------------------------------------------------------------
// Flash attention, causal, fp32. Output rounded to tf32 (feeds out-proj GEMM).
// ---------------------------------------------------------------------------
__global__ __launch_bounds__(256)
void flash_kernel()
{
    const int TK = 32;
    __shared__ float Ks[TK][HD];
    __shared__ float Vs[TK][HD];

    int bh = blockIdx.y;
    int q0 = blockIdx.x * 8;
    int w = threadIdx.x >> 5;
    int lane = threadIdx.x & 31;
    int qidx = q0 + w;

    const float* qptr = g_Q + ((long)bh * T_SEQ + qidx) * HD;
    float qr[4], o[4] = {0.f, 0.f, 0.f, 0.f};
#pragma unroll
    for (int i = 0; i < 4; i++) qr[i] = qptr[lane + 32 * i];

    float m = -INFINITY, ssum = 0.f;
    const float scale = 0.08838834764831845f;

    int nT = (q0 + 8 + TK - 1) / TK;
    const float* Kb = g_K + (long)bh * T_SEQ * HD;
    const float* Vb = g_V + (long)bh * T_SEQ * HD;

    for (int tile = 0; tile < nT; tile++) {
        int k0 = tile * TK;
        for (int i = threadIdx.x; i < TK * HD / 4; i += 256) {
            int r = i >> 5;
            int c = (i & 31) * 4;
            *(float4*)&Ks[r][c] = *(const float4*)(Kb + (long)(k0 + r) * HD + c);
            *(float4*)&Vs[r][c] = *(const float4*)(Vb + (long)(k0 + r) * HD + c);
        }
        __syncthreads();

        if (k0 <= qidx) {
            int kmax = min(TK, qidx - k0 + 1);
            for (int kk = 0; kk < kmax; kk++) {
                float p = qr[0] * Ks[kk][lane]      + qr[1] * Ks[kk][lane + 32]
                        + qr[2] * Ks[kk][lane + 64] + qr[3] * Ks[kk][lane + 96];
                p += __shfl_xor_sync(0xffffffffu, p, 16);
                p += __shfl_xor_sync(0xffffffffu, p, 8);
                p += __shfl_xor_sync(0xffffffffu, p, 4);
                p += __shfl_xor_sync(0xffffffffu, p, 2);
                p += __shfl_xor_sync(0xffffffffu, p, 1);
                float s = p * scale;
                float newm = fmaxf(m, s);
                float alpha = __expf(m - newm);
                float pe = __expf(s - newm);
                ssum = ssum * alpha + pe;
#pragma unroll
                for (int i = 0; i < 4; i++)
                    o[i] = o[i] * alpha + pe * Vs[kk][lane + 32 * i];
                m = newm;
            }
        }
        __syncthreads();
    }

    float invs = 1.0f / ssum;
    int b = bh >> 4, h = bh & 15;
    float* yp = g_Y + ((long)(b * T_SEQ + qidx)) * DIMC + h * HD;
#pragma unroll
    for (int i = 0; i < 4; i++) yp[lane + 32 * i] = to_tf32(o[i] * invs);
}

// ---------------------------------------------------------------------------
extern "C" void kernel_launch(void* const* d_in, const int* in_sizes, int n_in,
                              void* d_out, int out_size)
{
    const float* x    = (const float*)d_in[0];   // [16,512,2048]
    const float* Wqkv = (const float*)d_in[1];   // [2048,6144]
    const float* Wout = (const float*)d_in[2];   // [2048,2048]
    float* out = (float*)d_out;                  // [16,512,2048]

    static int attr_done = 0;
    if (!attr_done) {
        cudaFuncSetAttribute(gemm_mma_kernel<0>,
                             cudaFuncAttributeMaxDynamicSharedMemorySize, GEMM_SMEM);
        cudaFuncSetAttribute(gemm_mma_kernel<1>,
                             cudaFuncAttributeMaxDynamicSharedMemorySize, GEMM_SMEM);
        attr_done = 1;
    }

    // 0) Round x; transpose + round weights
    round_x_kernel<<<NTOK * DIMC / 4 / 256, 256>>>(x);
    {
        dim3 blk(32, 8);
        transpose_kernel<0><<<dim3(N_QKV / 32, DIMC / 32), blk>>>(Wqkv, DIMC, N_QKV);
        transpose_kernel<1><<<dim3(DIMC / 32, DIMC / 32), blk>>>(Wout, DIMC, DIMC);
    }
    // 1) QKV projection (tf32 mma.sync) scatter -> g_Q/g_K/g_V
    {
        dim3 grid(N_QKV / 128, NTOK / 128);   // 48 x 64
        gemm_mma_kernel<0><<<grid, 256, GEMM_SMEM>>>(nullptr, N_QKV);
    }
    // 2) RoPE on Q,K
    {
        int total = BH * T_SEQ * 8;
        rope_kernel<<<(total + 255) / 256, 256>>>();
    }
    // 3) Causal flash attention -> g_Y (tf32-rounded)
    {
        dim3 grid(T_SEQ / 8, BH);
        flash_kernel<<<grid, 256>>>();
    }
    // 4) Output projection (tf32 mma.sync)
    {
        dim3 grid(DIMC / 128, NTOK / 128);    // 16 x 64
        gemm_mma_kernel<1><<<grid, 256, GEMM_SMEM>>>(out, DIMC);
    }
}

// round 5
// speedup vs baseline: 3.6273x; 1.8344x over previous
#include <cuda_runtime.h>
#include <math.h>

#define DIMC   2048
#define NH     16
#define HD     128
#define T_SEQ  512
#define BATCH  16
#define BH     (BATCH * NH)      // 256
#define NTOK   (BATCH * T_SEQ)   // 8192
#define N_QKV  (3 * DIMC)        // 6144
#define GKD    2048              // GEMM K dim (both GEMMs)

// Scratch (device globals; no allocations allowed)
__device__ float g_Q[BH * T_SEQ * HD];
__device__ float g_K[BH * T_SEQ * HD];
__device__ float g_V[BH * T_SEQ * HD];
__device__ float g_Y[NTOK * DIMC];        // attention output, tf32-rounded at write
__device__ float g_xr[NTOK * DIMC];       // x rounded to tf32
__device__ float g_WqkvT[N_QKV * DIMC];   // [6144][2048], tf32-rounded
__device__ float g_WoutT[DIMC * DIMC];    // [2048][2048], tf32-rounded

// ---------------------------------------------------------------------------
__device__ __forceinline__ float to_tf32(float x) {
    float y;
    asm("cvt.rna.tf32.f32 %0, %1;" : "=f"(y) : "f"(x));
    return y;
}

__device__ __forceinline__ unsigned smem_u32(const void* p) {
    unsigned a;
    asm("{ .reg .u64 t; cvta.to.shared.u64 t, %1; cvt.u32.u64 %0, t; }"
        : "=r"(a) : "l"(p));
    return a;
}

__device__ __forceinline__ void mma8(float* c,
                                     unsigned a0, unsigned a1, unsigned a2, unsigned a3,
                                     unsigned b0, unsigned b1) {
    asm volatile(
        "mma.sync.aligned.m16n8k8.row.col.f32.tf32.tf32.f32 "
        "{%0,%1,%2,%3}, {%4,%5,%6,%7}, {%8,%9}, {%0,%1,%2,%3};"
        : "+f"(c[0]), "+f"(c[1]), "+f"(c[2]), "+f"(c[3])
        : "r"(a0), "r"(a1), "r"(a2), "r"(a3), "r"(b0), "r"(b1));
}

// ---------------------------------------------------------------------------
// Pre-round x to tf32 (float4 vectorized)
// ---------------------------------------------------------------------------
__global__ void round_x_kernel(const float* __restrict__ x)
{
    int i = blockIdx.x * blockDim.x + threadIdx.x;      // float4 index
    float4 v = *(const float4*)(x + (long)i * 4);
    v.x = to_tf32(v.x); v.y = to_tf32(v.y);
    v.z = to_tf32(v.z); v.w = to_tf32(v.w);
    *(float4*)(g_xr + (long)i * 4) = v;
}

// ---------------------------------------------------------------------------
// Transpose + round: Wt[n][k] = tf32(W[k][n])
// ---------------------------------------------------------------------------
template <int WHICH>
__global__ void transpose_kernel(const float* __restrict__ W, int K, int N)
{
    __shared__ float t[32][33];
    float* Wt = (WHICH == 0) ? g_WqkvT : g_WoutT;
    int n0 = blockIdx.x * 32, k0 = blockIdx.y * 32;
    int tx = threadIdx.x, ty = threadIdx.y;  // 32 x 8
#pragma unroll
    for (int i = 0; i < 32; i += 8)
        t[ty + i][tx] = to_tf32(W[(long)(k0 + ty + i) * N + n0 + tx]);
    __syncthreads();
#pragma unroll
    for (int i = 0; i < 32; i += 8)
        Wt[(long)(n0 + ty + i) * K + k0 + tx] = t[tx][ty + i];
}

// ---------------------------------------------------------------------------
// TF32 mma.sync GEMM, 3-stage cp.async pipeline, one sync per iteration.
// BM=128 BN=128 BK=32, 256 thr, warps 4(M) x 2(N), warp tile 32x64.
// ---------------------------------------------------------------------------
#define BKP 36
#define TILE_F (128 * BKP)            // 4608 floats per tile
#define STAGE_F (2 * TILE_F)          // 9216 floats per stage
#define NSTAGE 3
#define GEMM_SMEM (NSTAGE * STAGE_F * 4)   // 110592 bytes

template <int MODE>
__global__ __launch_bounds__(256, 2)
void gemm_mma_kernel(float* __restrict__ Cmat, int N)
{
    extern __shared__ float sm[];

    const float* A  = (MODE == 0) ? g_xr : g_Y;
    const float* Bt = (MODE == 0) ? g_WqkvT : g_WoutT;

    int tid = threadIdx.x;
    int wid = tid >> 5;
    int lane = tid & 31;
    int g = lane >> 2;
    int tig = lane & 3;

    int bm = blockIdx.y * 128;
    int bn = blockIdx.x * 128;
    int wm = (wid & 3) * 32;
    int wn = (wid >> 2) * 64;

    const float* Arow = A + (long)bm * GKD;
    const float* Brow = Bt + (long)bn * GKD;

    float acc[2][8][4];
#pragma unroll
    for (int mt = 0; mt < 2; mt++)
#pragma unroll
        for (int nt = 0; nt < 8; nt++)
#pragma unroll
            for (int v = 0; v < 4; v++) acc[mt][nt][v] = 0.f;

    auto load_stage = [&](int it, int st) {
        float* dstA = sm + st * STAGE_F;
        float* dstB = dstA + TILE_F;
        int k0 = it * 32;
#pragma unroll
        for (int i = 0; i < 4; i++) {
            int id = tid + 256 * i;          // 0..1023
            int r = id >> 3, ch = id & 7;
            unsigned da = smem_u32(dstA + r * BKP + ch * 4);
            const float* sa = Arow + (long)r * GKD + k0 + ch * 4;
            asm volatile("cp.async.cg.shared.global [%0], [%1], 16;"
                         :: "r"(da), "l"(sa));
            unsigned db = smem_u32(dstB + r * BKP + ch * 4);
            const float* sb = Brow + (long)r * GKD + k0 + ch * 4;
            asm volatile("cp.async.cg.shared.global [%0], [%1], 16;"
                         :: "r"(db), "l"(sb));
        }
        asm volatile("cp.async.commit_group;" ::: "memory");
    };

    auto compute = [&](const float* s) {
        const float* As = s;
        const float* Bs = s + TILE_F;
#pragma unroll
        for (int ks = 0; ks < 32; ks += 8) {
            unsigned a[2][4];
#pragma unroll
            for (int mt = 0; mt < 2; mt++) {
                int r = wm + 16 * mt + g;
                a[mt][0] = __float_as_uint(As[r * BKP + ks + tig]);
                a[mt][1] = __float_as_uint(As[(r + 8) * BKP + ks + tig]);
                a[mt][2] = __float_as_uint(As[r * BKP + ks + tig + 4]);
                a[mt][3] = __float_as_uint(As[(r + 8) * BKP + ks + tig + 4]);
            }
#pragma unroll
            for (int nt = 0; nt < 8; nt++) {
                int rn = wn + 8 * nt + g;
                unsigned b0 = __float_as_uint(Bs[rn * BKP + ks + tig]);
                unsigned b1 = __float_as_uint(Bs[rn * BKP + ks + tig + 4]);
#pragma unroll
                for (int mt = 0; mt < 2; mt++)
                    mma8(acc[mt][nt], a[mt][0], a[mt][1], a[mt][2], a[mt][3], b0, b1);
            }
        }
    };

    const int NIT = GKD / 32;     // 64
    load_stage(0, 0);
    load_stage(1, 1);

    for (int it = 0; it < NIT; it++) {
        asm volatile("cp.async.wait_group 1;" ::: "memory");
        __syncthreads();
        if (it + 2 < NIT) load_stage(it + 2, (it + 2) % NSTAGE);
        compute(sm + (it % NSTAGE) * STAGE_F);
    }

    // epilogue
#pragma unroll
    for (int mt = 0; mt < 2; mt++) {
#pragma unroll
        for (int nt = 0; nt < 8; nt++) {
            int col = bn + wn + 8 * nt + 2 * tig;
#pragma unroll
            for (int half = 0; half < 2; half++) {
                int m = bm + wm + 16 * mt + g + 8 * half;
                float2 v = make_float2(acc[mt][nt][2 * half],
                                       acc[mt][nt][2 * half + 1]);
                if (MODE == 0) {
                    int which = col >> 11;
                    int rm = col & 2047;
                    int h = rm >> 7, d = rm & 127;
                    float* dst = (which == 0) ? g_Q : (which == 1) ? g_K : g_V;
                    *(float2*)(dst + (((long)((m >> 9) * NH + h)) * T_SEQ
                                      + (m & 511)) * HD + d) = v;
                } else {
                    *(float2*)(Cmat + (long)m * N + col) = v;
                }
            }
        }
    }
}

// ---------------------------------------------------------------------------
// RoPE in-place on g_Q, g_K (first 16 dims of each head).
// ---------------------------------------------------------------------------
__global__ void rope_kernel()
{
    int idx = blockIdx.x * blockDim.x + threadIdx.x;
    const int total = BH * T_SEQ * 8;
    if (idx >= total) return;
    int i = idx & 7;
    int bht = idx >> 3;
    int t = bht % T_SEQ;

    float inv = powf(10000.0f, -(float)i / 8.0f);
    float fr = (float)t * inv;
    float s, c;
    sincosf(fr, &s, &c);

    float* q = g_Q + (long)bht * HD;
    float x1 = q[i], x2 = q[i + 8];
    q[i]     = x1 * c - x2 * s;
    q[i + 8] = x2 * c + x1 * s;

    float* k = g_K + (long)bht * HD;
    x1 = k[i]; x2 = k[i + 8];
    k[i]     = x1 * c - x2 * s;
    k[i + 8] = x2 * c + x1 * s;
}

// ---------------------------------------------------------------------------
// FA2-style flash attention with tf32 mma.sync.
// CTA: one (b,h) x 128-query tile. 8 warps x 16 rows. Key tiles of 64.
// ---------------------------------------------------------------------------
#define LDQ 132
#define LDV 68
#define FLASH_SMEM ((128 * LDQ + 64 * LDQ + 128 * LDV) * 4)   // 136192 B

__global__ __launch_bounds__(256)
void flash_mma_kernel()
{
    extern __shared__ float fsm[];
    float* Qs = fsm;                       // [128][LDQ]
    float* Ks = fsm + 128 * LDQ;           // [64][LDQ]
    float* Vt = Ks + 64 * LDQ;             // [128][LDV]  (dim-major: Vt[d][k])

    int bh = blockIdx.y;
    int q0 = blockIdx.x * 128;
    int tid = threadIdx.x;
    int wid = tid >> 5;
    int lane = tid & 31;
    int g = lane >> 2;
    int tig = lane & 3;
    int wm = wid * 16;

    const float* Qg = g_Q + (long)bh * T_SEQ * HD;
    const float* Kg = g_K + (long)bh * T_SEQ * HD;
    const float* Vg = g_V + (long)bh * T_SEQ * HD;

    // load Q tile (rounded to tf32)
    for (int i = tid; i < 128 * 32; i += 256) {
        int r = i >> 5, c4 = (i & 31) * 4;
        float4 v = *(const float4*)(Qg + (long)(q0 + r) * HD + c4);
        Qs[r * LDQ + c4 + 0] = to_tf32(v.x);
        Qs[r * LDQ + c4 + 1] = to_tf32(v.y);
        Qs[r * LDQ + c4 + 2] = to_tf32(v.z);
        Qs[r * LDQ + c4 + 3] = to_tf32(v.w);
    }

    float acc_o[16][4];
#pragma unroll
    for (int nto = 0; nto < 16; nto++)
#pragma unroll
        for (int v = 0; v < 4; v++) acc_o[nto][v] = 0.f;
    float mrow0 = -1e30f, mrow1 = -1e30f;
    float lrow0 = 0.f, lrow1 = 0.f;

    const float scale = 0.08838834764831845f;  // 1/sqrt(128)
    const unsigned FULL = 0xffffffffu;
    int nkt = q0 / 64 + 2;

    for (int kt = 0; kt < nkt; kt++) {
        int k0 = kt * 64;
        __syncthreads();   // protect Ks/Vt reuse
        // K tile: [64][128] rounded
        for (int i = tid; i < 64 * 32; i += 256) {
            int r = i >> 5, c4 = (i & 31) * 4;
            float4 v = *(const float4*)(Kg + (long)(k0 + r) * HD + c4);
            Ks[r * LDQ + c4 + 0] = to_tf32(v.x);
            Ks[r * LDQ + c4 + 1] = to_tf32(v.y);
            Ks[r * LDQ + c4 + 2] = to_tf32(v.z);
            Ks[r * LDQ + c4 + 3] = to_tf32(v.w);
        }
        // V tile transposed: Vt[d][k] (conflict-free stores: lanes span keys)
        for (int i = tid; i < 64 * 32; i += 256) {
            int r = i & 63;            // key
            int d4 = (i >> 6) * 4;     // dim
            float4 v = *(const float4*)(Vg + (long)(k0 + r) * HD + d4);
            Vt[(d4 + 0) * LDV + r] = to_tf32(v.x);
            Vt[(d4 + 1) * LDV + r] = to_tf32(v.y);
            Vt[(d4 + 2) * LDV + r] = to_tf32(v.z);
            Vt[(d4 + 3) * LDV + r] = to_tf32(v.w);
        }
        __syncthreads();

        if (k0 <= q0 + wm + 15) {      // warp has unmasked rows in this tile
            // ---- S = Q K^T ----
            float s[8][4];
#pragma unroll
            for (int nt = 0; nt < 8; nt++)
#pragma unroll
                for (int v = 0; v < 4; v++) s[nt][v] = 0.f;
#pragma unroll
            for (int ks = 0; ks < 16; ks++) {
                int kd = ks * 8;
                unsigned a0 = __float_as_uint(Qs[(wm + g) * LDQ + kd + tig]);
                unsigned a1 = __float_as_uint(Qs[(wm + g + 8) * LDQ + kd + tig]);
                unsigned a2 = __float_as_uint(Qs[(wm + g) * LDQ + kd + tig + 4]);
                unsigned a3 = __float_as_uint(Qs[(wm + g + 8) * LDQ + kd + tig + 4]);
#pragma unroll
                for (int nt = 0; nt < 8; nt++) {
                    unsigned b0 = __float_as_uint(Ks[(8 * nt + g) * LDQ + kd + tig]);
                    unsigned b1 = __float_as_uint(Ks[(8 * nt + g) * LDQ + kd + tig + 4]);
                    mma8(s[nt], a0, a1, a2, a3, b0, b1);
                }
            }
            // ---- scale + causal mask ----
            int r0 = q0 + wm + g;
            int r1 = r0 + 8;
#pragma unroll
            for (int nt = 0; nt < 8; nt++) {
                int c0 = k0 + 8 * nt + 2 * tig;
                int c1 = c0 + 1;
                s[nt][0] = (c0 <= r0) ? s[nt][0] * scale : -1e30f;
                s[nt][1] = (c1 <= r0) ? s[nt][1] * scale : -1e30f;
                s[nt][2] = (c0 <= r1) ? s[nt][2] * scale : -1e30f;
                s[nt][3] = (c1 <= r1) ? s[nt][3] * scale : -1e30f;
            }
            // ---- row max (quad reduce) ----
            float mx0 = -1e30f, mx1 = -1e30f;
#pragma unroll
            for (int nt = 0; nt < 8; nt++) {
                mx0 = fmaxf(mx0, fmaxf(s[nt][0], s[nt][1]));
                mx1 = fmaxf(mx1, fmaxf(s[nt][2], s[nt][3]));
            }
            mx0 = fmaxf(mx0, __shfl_xor_sync(FULL, mx0, 1));
            mx0 = fmaxf(mx0, __shfl_xor_sync(FULL, mx0, 2));
            mx1 = fmaxf(mx1, __shfl_xor_sync(FULL, mx1, 1));
            mx1 = fmaxf(mx1, __shfl_xor_sync(FULL, mx1, 2));
            float mn0 = fmaxf(mrow0, mx0);
            float mn1 = fmaxf(mrow1, mx1);
            float al0 = __expf(mrow0 - mn0);
            float al1 = __expf(mrow1 - mn1);
            mrow0 = mn0; mrow1 = mn1;
            // ---- exp + row sums ----
            float sum0 = 0.f, sum1 = 0.f;
#pragma unroll
            for (int nt = 0; nt < 8; nt++) {
                s[nt][0] = __expf(s[nt][0] - mn0);
                s[nt][1] = __expf(s[nt][1] - mn0);
                s[nt][2] = __expf(s[nt][2] - mn1);
                s[nt][3] = __expf(s[nt][3] - mn1);
                sum0 += s[nt][0] + s[nt][1];
                sum1 += s[nt][2] + s[nt][3];
            }
            sum0 += __shfl_xor_sync(FULL, sum0, 1);
            sum0 += __shfl_xor_sync(FULL, sum0, 2);
            sum1 += __shfl_xor_sync(FULL, sum1, 1);
            sum1 += __shfl_xor_sync(FULL, sum1, 2);
            lrow0 = lrow0 * al0 + sum0;
            lrow1 = lrow1 * al1 + sum1;
            // ---- rescale O ----
#pragma unroll
            for (int nto = 0; nto < 16; nto++) {
                acc_o[nto][0] *= al0; acc_o[nto][1] *= al0;
                acc_o[nto][2] *= al1; acc_o[nto][3] *= al1;
            }
            // ---- PV: rearrange P into A-fragments via quad shfls ----
            int src0 = (lane & ~3) | (tig >> 1);
            int src1 = src0 + 2;
            int sel = tig & 1;
#pragma unroll
            for (int kk = 0; kk < 8; kk++) {
                float x0 = __shfl_sync(FULL, s[kk][0], src0);
                float x1 = __shfl_sync(FULL, s[kk][1], src0);
                float x2 = __shfl_sync(FULL, s[kk][2], src0);
                float x3 = __shfl_sync(FULL, s[kk][3], src0);
                float y0 = __shfl_sync(FULL, s[kk][0], src1);
                float y1 = __shfl_sync(FULL, s[kk][1], src1);
                float y2 = __shfl_sync(FULL, s[kk][2], src1);
                float y3 = __shfl_sync(FULL, s[kk][3], src1);
                unsigned a0 = __float_as_uint(to_tf32(sel ? x1 : x0)); // P[g][tig]
                unsigned a1 = __float_as_uint(to_tf32(sel ? x3 : x2)); // P[g+8][tig]
                unsigned a2 = __float_as_uint(to_tf32(sel ? y1 : y0)); // P[g][tig+4]
                unsigned a3 = __float_as_uint(to_tf32(sel ? y3 : y2)); // P[g+8][tig+4]
#pragma unroll
                for (int nto = 0; nto < 16; nto++) {
                    unsigned b0 = __float_as_uint(Vt[(8 * nto + g) * LDV + 8 * kk + tig]);
                    unsigned b1 = __float_as_uint(Vt[(8 * nto + g) * LDV + 8 * kk + tig + 4]);
                    mma8(acc_o[nto], a0, a1, a2, a3, b0, b1);
                }
            }
        }
    }

    // ---- finalize + write (tf32-rounded, feeds out-proj GEMM) ----
    float inv0 = 1.f / lrow0;
    float inv1 = 1.f / lrow1;
    int b = bh >> 4, h = bh & 15;
    int r0 = q0 + wm + g;
    int r1 = r0 + 8;
    float* y0 = g_Y + ((long)(b * T_SEQ + r0)) * DIMC + h * HD;
    float* y1 = g_Y + ((long)(b * T_SEQ + r1)) * DIMC + h * HD;
#pragma unroll
    for (int nto = 0; nto < 16; nto++) {
        int d = 8 * nto + 2 * tig;
        float2 v0 = make_float2(to_tf32(acc_o[nto][0] * inv0),
                                to_tf32(acc_o[nto][1] * inv0));
        *(float2*)(y0 + d) = v0;
        float2 v1 = make_float2(to_tf32(acc_o[nto][2] * inv1),
                                to_tf32(acc_o[nto][3] * inv1));
        *(float2*)(y1 + d) = v1;
    }
}

// ---------------------------------------------------------------------------
extern "C" void kernel_launch(void* const* d_in, const int* in_sizes, int n_in,
                              void* d_out, int out_size)
{
    const float* x    = (const float*)d_in[0];
    const float* Wqkv = (const float*)d_in[1];
    const float* Wout = (const float*)d_in[2];
    float* out = (float*)d_out;

    static int attr_done = 0;
    if (!attr_done) {
        cudaFuncSetAttribute(gemm_mma_kernel<0>,
                             cudaFuncAttributeMaxDynamicSharedMemorySize, GEMM_SMEM);
        cudaFuncSetAttribute(gemm_mma_kernel<1>,
                             cudaFuncAttributeMaxDynamicSharedMemorySize, GEMM_SMEM);
        cudaFuncSetAttribute(flash_mma_kernel,
                             cudaFuncAttributeMaxDynamicSharedMemorySize, FLASH_SMEM);
        attr_done = 1;
    }

    // 0) Round x; transpose + round weights
    round_x_kernel<<<NTOK * DIMC / 4 / 256, 256>>>(x);
    {
        dim3 blk(32, 8);
        transpose_kernel<0><<<dim3(N_QKV / 32, DIMC / 32), blk>>>(Wqkv, DIMC, N_QKV);
        transpose_kernel<1><<<dim3(DIMC / 32, DIMC / 32), blk>>>(Wout, DIMC, DIMC);
    }
    // 1) QKV projection (tf32 mma) scatter -> g_Q/g_K/g_V
    {
        dim3 grid(N_QKV / 128, NTOK / 128);   // 48 x 64
        gemm_mma_kernel<0><<<grid, 256, GEMM_SMEM>>>(nullptr, N_QKV);
    }
    // 2) RoPE on Q,K
    {
        int total = BH * T_SEQ * 8;
        rope_kernel<<<(total + 255) / 256, 256>>>();
    }
    // 3) Causal flash attention (tf32 mma) -> g_Y
    {
        dim3 grid(T_SEQ / 128, BH);           // 4 x 256
        flash_mma_kernel<<<grid, 256, FLASH_SMEM>>>();
    }
    // 4) Output projection (tf32 mma)
    {
        dim3 grid(DIMC / 128, NTOK / 128);    // 16 x 64
        gemm_mma_kernel<1><<<grid, 256, GEMM_SMEM>>>(out, DIMC);
    }
}